// round 9
// baseline (speedup 1.0000x reference)
#include <cuda_runtime.h>
#include <cuda_bf16.h>
#include <math.h>
#include <stdint.h>

#define BATCH    64
#define IN_SIZE  1024
#define IN_DIM   256
#define HEADS    4
#define OUT_SIZE 64
#define OUT_DIM  256
#define NMAT     (BATCH * HEADS)     /* 256 */
#define HID      (HEADS * IN_DIM)    /* 1024 */
#define MAX_ITER 10

// ---------------------------------------------------------------------------
// Scratch
// ---------------------------------------------------------------------------
__device__ float g_K[(size_t)NMAT * IN_SIZE * OUT_SIZE];        // 64 MB [n][s][o]
__device__ float g_u[(size_t)NMAT * IN_SIZE];
__device__ float g_v[(size_t)NMAT * OUT_SIZE];
__device__ __nv_bfloat16 g_xT_hi[(size_t)BATCH * IN_DIM * IN_SIZE];   // [b][d][s]
__device__ __nv_bfloat16 g_xT_lo[(size_t)BATCH * IN_DIM * IN_SIZE];
__device__ __nv_bfloat16 g_kT_hi[(size_t)NMAT * OUT_SIZE * IN_SIZE];  // [n][o][s]
__device__ __nv_bfloat16 g_kT_lo[(size_t)NMAT * OUT_SIZE * IN_SIZE];
__device__ __nv_bfloat16 g_att_hi[(size_t)BATCH * OUT_SIZE * HID];    // [m][k] m=b*64+o
__device__ __nv_bfloat16 g_att_lo[(size_t)BATCH * OUT_SIZE * HID];
__device__ __nv_bfloat16 g_lw_hi[(size_t)OUT_DIM * HID];              // [nn][k]
__device__ __nv_bfloat16 g_lw_lo[(size_t)OUT_DIM * HID];

// ---------------------------------------------------------------------------
// Helpers (base-target PTX only)
// ---------------------------------------------------------------------------
__device__ __forceinline__ uint32_t smem_u32(const void* p) {
    uint32_t a;
    asm("{ .reg .u64 t; cvta.to.shared.u64 t, %1; cvt.u32.u64 %0, t; }" : "=r"(a) : "l"(p));
    return a;
}
__device__ __forceinline__ void ldsm4(uint32_t* r, uint32_t a) {
    asm volatile("ldmatrix.sync.aligned.m8n8.x4.shared.b16 {%0,%1,%2,%3}, [%4];"
        : "=r"(r[0]), "=r"(r[1]), "=r"(r[2]), "=r"(r[3]) : "r"(a));
}
__device__ __forceinline__ void ldsm2(uint32_t* r, uint32_t a) {
    asm volatile("ldmatrix.sync.aligned.m8n8.x2.shared.b16 {%0,%1}, [%2];"
        : "=r"(r[0]), "=r"(r[1]) : "r"(a));
}
__device__ __forceinline__ void mma16816(float* c, const uint32_t* a, const uint32_t* b) {
    asm volatile(
        "mma.sync.aligned.m16n8k16.row.col.f32.bf16.bf16.f32 "
        "{%0,%1,%2,%3}, {%4,%5,%6,%7}, {%8,%9}, {%0,%1,%2,%3};"
        : "+f"(c[0]), "+f"(c[1]), "+f"(c[2]), "+f"(c[3])
        : "r"(a[0]), "r"(a[1]), "r"(a[2]), "r"(a[3]), "r"(b[0]), "r"(b[1]));
}
__device__ __forceinline__ uint32_t pack2(__nv_bfloat16 a, __nv_bfloat16 b) {
    uint16_t ua = *(uint16_t*)&a, ub = *(uint16_t*)&b;
    return (uint32_t)ua | ((uint32_t)ub << 16);
}
__device__ __forceinline__ void split2(float f, __nv_bfloat16& h, __nv_bfloat16& l) {
    h = __float2bfloat16(f);
    l = __float2bfloat16(f - __bfloat162float(h));
}

// Padded bf16 SMEM tiles: row stride 72 elems (144 B) — 16B-aligned ldmatrix rows.
#define RS 72
#define OFF_AH 0
#define OFF_AL (128 * RS * 2)
#define OFF_BH (2 * 128 * RS * 2)
#define OFF_BL (2 * 128 * RS * 2 + 64 * RS * 2)
#define DSMEM_BYTES (2 * 128 * RS * 2 + 2 * 64 * RS * 2)   /* 55296 */

// ---------------------------------------------------------------------------
// Kernel 1: K = exp(10 * x·Wᵀ), bf16 split-2 HMMA. M=128(s) N=64(o) K=256(d).
// ---------------------------------------------------------------------------
__global__ __launch_bounds__(256) void gemm_k_mma(const float* __restrict__ x,
                                                  const float* __restrict__ W) {
    extern __shared__ char dyn[];
    __nv_bfloat16* Ah = (__nv_bfloat16*)(dyn + OFF_AH);
    __nv_bfloat16* Al = (__nv_bfloat16*)(dyn + OFF_AL);
    __nv_bfloat16* Bh = (__nv_bfloat16*)(dyn + OFF_BH);
    __nv_bfloat16* Bl = (__nv_bfloat16*)(dyn + OFF_BL);

    int tid = threadIdx.x, lane = tid & 31, wid = tid >> 5;
    int wm = wid & 3, wn = wid >> 2;
    int n = blockIdx.y, b = n >> 2, h = n & 3;
    int s0 = blockIdx.x * 128;
    const float* xg = x + ((size_t)b * IN_SIZE + s0) * IN_DIM;
    const float* wg = W + (size_t)h * OUT_SIZE * IN_DIM;

    uint32_t aBaseH = smem_u32(Ah) + ((wm * 32 + (lane & 15)) * RS + (lane >> 4) * 8) * 2;
    uint32_t aBaseL = aBaseH + (OFF_AL - OFF_AH);
    uint32_t bBaseH = smem_u32(Bh) + ((wn * 32 + (lane & 7)) * RS + ((lane >> 3) & 1) * 8) * 2;
    uint32_t bBaseL = bBaseH + (OFF_BL - OFF_BH);

    float c[2][4][4];
    #pragma unroll
    for (int f = 0; f < 2; ++f)
        #pragma unroll
        for (int g = 0; g < 4; ++g)
            #pragma unroll
            for (int q = 0; q < 4; ++q) c[f][g][q] = 0.f;

    for (int ch = 0; ch < 4; ++ch) {
        int d0 = ch * 64;
        #pragma unroll
        for (int i = 0; i < 8; ++i) {
            int vi = i * 256 + tid;
            int row = vi >> 4, c4 = (vi & 15) * 4;
            float4 v = *(const float4*)(xg + (size_t)row * IN_DIM + d0 + c4);
            __nv_bfloat16 h0, h1, h2, h3, l0, l1, l2, l3;
            split2(v.x, h0, l0); split2(v.y, h1, l1);
            split2(v.z, h2, l2); split2(v.w, h3, l3);
            int off = row * RS + c4;
            *(uint2*)(Ah + off) = make_uint2(pack2(h0, h1), pack2(h2, h3));
            *(uint2*)(Al + off) = make_uint2(pack2(l0, l1), pack2(l2, l3));
        }
        #pragma unroll
        for (int i = 0; i < 4; ++i) {
            int vi = i * 256 + tid;
            int row = vi >> 4, c4 = (vi & 15) * 4;
            float4 v = *(const float4*)(wg + (size_t)row * IN_DIM + d0 + c4);
            __nv_bfloat16 h0, h1, h2, h3, l0, l1, l2, l3;
            split2(v.x, h0, l0); split2(v.y, h1, l1);
            split2(v.z, h2, l2); split2(v.w, h3, l3);
            int off = row * RS + c4;
            *(uint2*)(Bh + off) = make_uint2(pack2(h0, h1), pack2(h2, h3));
            *(uint2*)(Bl + off) = make_uint2(pack2(l0, l1), pack2(l2, l3));
        }
        __syncthreads();
        #pragma unroll
        for (int ks = 0; ks < 4; ++ks) {
            uint32_t ah[2][4], al[2][4], bh[4][2], bl[4][2];
            #pragma unroll
            for (int f = 0; f < 2; ++f) {
                uint32_t o = (uint32_t)(f * 16 * RS + ks * 16) * 2;
                ldsm4(ah[f], aBaseH + o);
                ldsm4(al[f], aBaseL + o);
            }
            #pragma unroll
            for (int g = 0; g < 4; ++g) {
                uint32_t o = (uint32_t)(g * 8 * RS + ks * 16) * 2;
                ldsm2(bh[g], bBaseH + o);
                ldsm2(bl[g], bBaseL + o);
            }
            #pragma unroll
            for (int f = 0; f < 2; ++f)
                #pragma unroll
                for (int g = 0; g < 4; ++g) {
                    mma16816(c[f][g], ah[f], bh[g]);
                    mma16816(c[f][g], ah[f], bl[g]);
                    mma16816(c[f][g], al[f], bh[g]);
                }
        }
        __syncthreads();
    }

    #pragma unroll
    for (int f = 0; f < 2; ++f) {
        int r0 = s0 + wm * 32 + f * 16 + (lane >> 2);
        #pragma unroll
        for (int g = 0; g < 4; ++g) {
            int o = wn * 32 + g * 8 + (lane & 3) * 2;
            float* p0 = g_K + ((size_t)n * IN_SIZE + r0) * OUT_SIZE + o;
            float* p1 = p0 + 8 * OUT_SIZE;
            *(float2*)p0 = make_float2(expf(c[f][g][0] * 10.f), expf(c[f][g][1] * 10.f));
            *(float2*)p1 = make_float2(expf(c[f][g][2] * 10.f), expf(c[f][g][3] * 10.f));
        }
    }
}

// ---------------------------------------------------------------------------
// Kernel 2: x[b][s][d] fp32 -> g_xT_hi/lo[b][d][s] bf16
// ---------------------------------------------------------------------------
__global__ __launch_bounds__(256) void xsplit_kernel(const float* __restrict__ x) {
    __shared__ float sm[64][65];
    int tid = threadIdx.x;
    int s0 = blockIdx.x * 64, d0 = blockIdx.y * 64, b = blockIdx.z;
    const float* xb = x + ((size_t)b * IN_SIZE + s0) * IN_DIM + d0;
    #pragma unroll
    for (int i = 0; i < 4; ++i) {
        int vi = i * 256 + tid;
        int rs = vi >> 4, c4 = (vi & 15) * 4;
        float4 v = *(const float4*)(xb + (size_t)rs * IN_DIM + c4);
        sm[rs][c4] = v.x; sm[rs][c4 + 1] = v.y; sm[rs][c4 + 2] = v.z; sm[rs][c4 + 3] = v.w;
    }
    __syncthreads();
    #pragma unroll
    for (int i = 0; i < 4; ++i) {
        int vi = i * 256 + tid;
        int rd = vi >> 4, s4 = (vi & 15) * 4;
        __nv_bfloat16 h[4], l[4];
        #pragma unroll
        for (int j = 0; j < 4; ++j) split2(sm[s4 + j][rd], h[j], l[j]);
        size_t off = ((size_t)b * IN_DIM + d0 + rd) * IN_SIZE + s0 + s4;
        *(uint2*)(g_xT_hi + off) = make_uint2(pack2(h[0], h[1]), pack2(h[2], h[3]));
        *(uint2*)(g_xT_lo + off) = make_uint2(pack2(l[0], l[1]), pack2(l[2], l[3]));
    }
}

// ---------------------------------------------------------------------------
// Kernel 3: Sinkhorn, 2-CTA cluster, K SMEM-resident.
// Cluster pair shares one n: rank r owns rows [r*512, r*512+512).
// Per iteration: fused u + v-partial pass over SMEM K, then DSMEM exchange of
// the 64 column partials (double-buffered by iteration parity).
// ---------------------------------------------------------------------------
__global__ void __cluster_dims__(2, 1, 1) __launch_bounds__(512, 1)
sinkhorn_cluster(const int* __restrict__ mask) {
    extern __shared__ float sK[];          // 512*64 fp32 = 128 KB
    __shared__ float sm_mask[512];
    __shared__ float sm_u[512];
    __shared__ float sm_v[OUT_SIZE];
    __shared__ float sm_vacc[16][OUT_SIZE];
    __shared__ float sm_exch[2][OUT_SIZE];
    __shared__ float sm_red[16];

    int tid = threadIdx.x, lane = tid & 31, wid = tid >> 5;
    uint32_t rank;
    asm("mov.u32 %0, %%cluster_ctarank;" : "=r"(rank));
    int n = blockIdx.x >> 1;
    int b = n >> 2;
    int srow0 = (int)rank * 512;

    // mask: local 512 for u, full 1024 sum for a
    const int* mb = mask + (size_t)b * IN_SIZE;
    float mloc = (mb[srow0 + tid] != 0) ? 1.f : 0.f;
    sm_mask[tid] = mloc;
    float mall = mloc + ((mb[(srow0 ^ 512) + tid] != 0) ? 1.f : 0.f);
    #pragma unroll
    for (int off = 16; off; off >>= 1) mall += __shfl_xor_sync(0xffffffffu, mall, off);
    if (lane == 0) sm_red[wid] = mall;
    if (tid < OUT_SIZE) sm_v[tid] = 1.0f;
    __syncthreads();
    float a;
    {
        float t = 0.f;
        #pragma unroll
        for (int w = 0; w < 16; ++w) t += sm_red[w];
        a = (float)OUT_SIZE / t;
    }

    // Load local K half: 512 rows x 64 cols fp32
    {
        const float4* g4 = (const float4*)(g_K + ((size_t)n * IN_SIZE + srow0) * OUT_SIZE);
        float4* s4 = (float4*)sK;
        #pragma unroll
        for (int i = 0; i < 16; ++i) s4[i * 512 + tid] = g4[i * 512 + tid];
    }
    __syncthreads();

    int o0 = lane * 2;
    int r0 = wid * 32;

    for (int it = 0; it < MAX_ITER; ++it) {
        float v0 = sm_v[o0], v1 = sm_v[o0 + 1];
        float va0 = 0.f, va1 = 0.f;
        #pragma unroll
        for (int rr = 0; rr < 32; rr += 4) {
            int r = r0 + rr;
            const float* base = sK + r * OUT_SIZE + o0;
            float2 k0 = *(const float2*)(base);
            float2 k1 = *(const float2*)(base + OUT_SIZE);
            float2 k2 = *(const float2*)(base + 2 * OUT_SIZE);
            float2 k3 = *(const float2*)(base + 3 * OUT_SIZE);
            float p0 = fmaf(k0.y, v1, k0.x * v0);
            float p1 = fmaf(k1.y, v1, k1.x * v0);
            float p2 = fmaf(k2.y, v1, k2.x * v0);
            float p3 = fmaf(k3.y, v1, k3.x * v0);
            #pragma unroll
            for (int off = 16; off; off >>= 1) {
                p0 += __shfl_xor_sync(0xffffffffu, p0, off);
                p1 += __shfl_xor_sync(0xffffffffu, p1, off);
                p2 += __shfl_xor_sync(0xffffffffu, p2, off);
                p3 += __shfl_xor_sync(0xffffffffu, p3, off);
            }
            float u0 = sm_mask[r + 0] * (a / p0);
            float u1 = sm_mask[r + 1] * (a / p1);
            float u2 = sm_mask[r + 2] * (a / p2);
            float u3 = sm_mask[r + 3] * (a / p3);
            if (lane == 0) {
                sm_u[r + 0] = u0; sm_u[r + 1] = u1;
                sm_u[r + 2] = u2; sm_u[r + 3] = u3;
            }
            va0 = fmaf(u0, k0.x, va0); va1 = fmaf(u0, k0.y, va1);
            va0 = fmaf(u1, k1.x, va0); va1 = fmaf(u1, k1.y, va1);
            va0 = fmaf(u2, k2.x, va0); va1 = fmaf(u2, k2.y, va1);
            va0 = fmaf(u3, k3.x, va0); va1 = fmaf(u3, k3.y, va1);
        }
        sm_vacc[wid][o0]     = va0;
        sm_vacc[wid][o0 + 1] = va1;
        __syncthreads();
        float own = 0.f;
        if (tid < OUT_SIZE) {
            #pragma unroll
            for (int w = 0; w < 16; ++w) own += sm_vacc[w][tid];
            sm_exch[it & 1][tid] = own;
        }
        // Cluster barrier: release own partial, acquire peer's (ALL threads).
        asm volatile("barrier.cluster.arrive.aligned;" ::: "memory");
        asm volatile("barrier.cluster.wait.aligned;" ::: "memory");
        if (tid < OUT_SIZE) {
            uint32_t la = smem_u32(&sm_exch[it & 1][tid]);
            uint32_t pa;
            asm("mapa.shared::cluster.u32 %0, %1, %2;" : "=r"(pa) : "r"(la), "r"(1u - rank));
            float pv;
            asm volatile("ld.shared::cluster.f32 %0, [%1];" : "=f"(pv) : "r"(pa));
            sm_v[tid] = 1.0f / (own + pv);
        }
        __syncthreads();
    }

    g_u[(size_t)n * IN_SIZE + srow0 + tid] = sm_u[tid];
    if (rank == 0 && tid < OUT_SIZE) g_v[(size_t)n * OUT_SIZE + tid] = sm_v[tid];
    // Final cluster barrier: no CTA may exit while peer might still read DSMEM.
    asm volatile("barrier.cluster.arrive.aligned;" ::: "memory");
    asm volatile("barrier.cluster.wait.aligned;" ::: "memory");
}

// ---------------------------------------------------------------------------
// Kernel 4: (u⊙K)ᵀ split: g_kT_hi/lo[n][o][s] bf16
// ---------------------------------------------------------------------------
__global__ __launch_bounds__(256) void kut_kernel() {
    __shared__ float sm[64][65];
    int tid = threadIdx.x;
    int s0 = blockIdx.x * 64, n = blockIdx.y;
    const float* Kn = g_K + ((size_t)n * IN_SIZE + s0) * OUT_SIZE;
    const float* un = g_u + (size_t)n * IN_SIZE + s0;
    #pragma unroll
    for (int i = 0; i < 4; ++i) {
        int vi = i * 256 + tid;
        int rs = vi >> 4, o4 = (vi & 15) * 4;
        float u = un[rs];
        float4 v = *(const float4*)(Kn + (size_t)rs * OUT_SIZE + o4);
        sm[rs][o4] = v.x * u; sm[rs][o4 + 1] = v.y * u;
        sm[rs][o4 + 2] = v.z * u; sm[rs][o4 + 3] = v.w * u;
    }
    __syncthreads();
    #pragma unroll
    for (int i = 0; i < 4; ++i) {
        int vi = i * 256 + tid;
        int ro = vi >> 4, s4 = (vi & 15) * 4;
        __nv_bfloat16 h[4], l[4];
        #pragma unroll
        for (int j = 0; j < 4; ++j) split2(sm[s4 + j][ro], h[j], l[j]);
        size_t off = ((size_t)n * OUT_SIZE + ro) * IN_SIZE + s0 + s4;
        *(uint2*)(g_kT_hi + off) = make_uint2(pack2(h[0], h[1]), pack2(h[2], h[3]));
        *(uint2*)(g_kT_lo + off) = make_uint2(pack2(l[0], l[1]), pack2(l[2], l[3]));
    }
}

// ---------------------------------------------------------------------------
// Kernel 5: attention: D[d,o] = Σ_s xT[d,s]·(uK)T[o,s]; att bf16 hi/lo out.
// ---------------------------------------------------------------------------
__global__ __launch_bounds__(256) void attn_mma() {
    extern __shared__ char dyn[];
    __nv_bfloat16* Ah = (__nv_bfloat16*)(dyn + OFF_AH);
    __nv_bfloat16* Al = (__nv_bfloat16*)(dyn + OFF_AL);
    __nv_bfloat16* Bh = (__nv_bfloat16*)(dyn + OFF_BH);
    __nv_bfloat16* Bl = (__nv_bfloat16*)(dyn + OFF_BL);
    __shared__ float s_v[OUT_SIZE];

    int tid = threadIdx.x, lane = tid & 31, wid = tid >> 5;
    int wm = wid & 3, wn = wid >> 2;
    int n = blockIdx.y, b = n >> 2, h = n & 3;
    int d0 = blockIdx.x * 128;

    if (tid < OUT_SIZE) s_v[tid] = g_v[(size_t)n * OUT_SIZE + tid];

    const __nv_bfloat16* xh = g_xT_hi + ((size_t)b * IN_DIM + d0) * IN_SIZE;
    const __nv_bfloat16* xl = g_xT_lo + ((size_t)b * IN_DIM + d0) * IN_SIZE;
    const __nv_bfloat16* kh = g_kT_hi + (size_t)n * OUT_SIZE * IN_SIZE;
    const __nv_bfloat16* kl = g_kT_lo + (size_t)n * OUT_SIZE * IN_SIZE;

    uint32_t aBaseH = smem_u32(Ah) + ((wm * 32 + (lane & 15)) * RS + (lane >> 4) * 8) * 2;
    uint32_t aBaseL = aBaseH + (OFF_AL - OFF_AH);
    uint32_t bBaseH = smem_u32(Bh) + ((wn * 32 + (lane & 7)) * RS + ((lane >> 3) & 1) * 8) * 2;
    uint32_t bBaseL = bBaseH + (OFF_BL - OFF_BH);

    float c[2][4][4];
    #pragma unroll
    for (int f = 0; f < 2; ++f)
        #pragma unroll
        for (int g = 0; g < 4; ++g)
            #pragma unroll
            for (int q = 0; q < 4; ++q) c[f][g][q] = 0.f;

    for (int ch = 0; ch < 16; ++ch) {
        int s0 = ch * 64;
        #pragma unroll
        for (int i = 0; i < 4; ++i) {
            int vi = i * 256 + tid;
            int row = vi >> 3, cu = vi & 7;
            size_t goff = (size_t)row * IN_SIZE + s0 + cu * 8;
            int off = row * RS + cu * 8;
            *(uint4*)(Ah + off) = *(const uint4*)(xh + goff);
            *(uint4*)(Al + off) = *(const uint4*)(xl + goff);
        }
        #pragma unroll
        for (int i = 0; i < 2; ++i) {
            int vi = i * 256 + tid;
            int row = vi >> 3, cu = vi & 7;
            size_t goff = (size_t)row * IN_SIZE + s0 + cu * 8;
            int off = row * RS + cu * 8;
            *(uint4*)(Bh + off) = *(const uint4*)(kh + goff);
            *(uint4*)(Bl + off) = *(const uint4*)(kl + goff);
        }
        __syncthreads();
        #pragma unroll
        for (int ks = 0; ks < 4; ++ks) {
            uint32_t ah[2][4], al[2][4], bh[4][2], bl[4][2];
            #pragma unroll
            for (int f = 0; f < 2; ++f) {
                uint32_t o = (uint32_t)(f * 16 * RS + ks * 16) * 2;
                ldsm4(ah[f], aBaseH + o);
                ldsm4(al[f], aBaseL + o);
            }
            #pragma unroll
            for (int g = 0; g < 4; ++g) {
                uint32_t o = (uint32_t)(g * 8 * RS + ks * 16) * 2;
                ldsm2(bh[g], bBaseH + o);
                ldsm2(bl[g], bBaseL + o);
            }
            #pragma unroll
            for (int f = 0; f < 2; ++f)
                #pragma unroll
                for (int g = 0; g < 4; ++g) {
                    mma16816(c[f][g], ah[f], bh[g]);
                    mma16816(c[f][g], ah[f], bl[g]);
                    mma16816(c[f][g], al[f], bh[g]);
                }
        }
        __syncthreads();
    }

    // Epilogue: v-scale, transpose via SMEM, emit bf16 hi/lo att[m][k]
    float* smF = (float*)dyn;   // 128 x 65 fp32 = 33280 B (fits in dyn)
    #pragma unroll
    for (int f = 0; f < 2; ++f) {
        int dl = wm * 32 + f * 16 + (lane >> 2);
        #pragma unroll
        for (int g = 0; g < 4; ++g) {
            int o = wn * 32 + g * 8 + (lane & 3) * 2;
            smF[dl * 65 + o]           = s_v[o]     * c[f][g][0];
            smF[dl * 65 + o + 1]       = s_v[o + 1] * c[f][g][1];
            smF[(dl + 8) * 65 + o]     = s_v[o]     * c[f][g][2];
            smF[(dl + 8) * 65 + o + 1] = s_v[o + 1] * c[f][g][3];
        }
    }
    __syncthreads();
    {
        int o = tid >> 2;               // 0..63
        int dseg = (tid & 3) * 32;      // 0,32,64,96
        size_t rowbase = ((size_t)b * OUT_SIZE + o) * HID + (size_t)h * IN_DIM + d0 + dseg;
        #pragma unroll
        for (int j = 0; j < 8; ++j) {
            float f0 = smF[(dseg + 4 * j + 0) * 65 + o];
            float f1 = smF[(dseg + 4 * j + 1) * 65 + o];
            float f2 = smF[(dseg + 4 * j + 2) * 65 + o];
            float f3 = smF[(dseg + 4 * j + 3) * 65 + o];
            __nv_bfloat16 h0, h1, h2, h3, l0, l1, l2, l3;
            split2(f0, h0, l0); split2(f1, h1, l1);
            split2(f2, h2, l2); split2(f3, h3, l3);
            *(uint2*)(g_att_hi + rowbase + 4 * j) = make_uint2(pack2(h0, h1), pack2(h2, h3));
            *(uint2*)(g_att_lo + rowbase + 4 * j) = make_uint2(pack2(l0, l1), pack2(l2, l3));
        }
    }
}

// ---------------------------------------------------------------------------
// Kernel 6: lin_w fp32 [256][1024] -> bf16 hi/lo (K-major, no transpose)
// ---------------------------------------------------------------------------
__global__ __launch_bounds__(256) void lwsplit_kernel(const float* __restrict__ lw) {
    int i = blockIdx.x * 256 + threadIdx.x;   // 4 floats each
    float4 v = *(const float4*)(lw + (size_t)i * 4);
    __nv_bfloat16 h0, h1, h2, h3, l0, l1, l2, l3;
    split2(v.x, h0, l0); split2(v.y, h1, l1);
    split2(v.z, h2, l2); split2(v.w, h3, l3);
    *(uint2*)(g_lw_hi + (size_t)i * 4) = make_uint2(pack2(h0, h1), pack2(h2, h3));
    *(uint2*)(g_lw_lo + (size_t)i * 4) = make_uint2(pack2(l0, l1), pack2(l2, l3));
}

// ---------------------------------------------------------------------------
// Kernel 7: out = relu(att @ lin_wᵀ + lin_b), bf16 split-2 HMMA.
// M=128(m) N=64(nn) K=1024, 16 chunks of 64.
// ---------------------------------------------------------------------------
__global__ __launch_bounds__(256) void linear_mma(const float* __restrict__ lb,
                                                  float* __restrict__ out) {
    extern __shared__ char dyn[];
    __nv_bfloat16* Ah = (__nv_bfloat16*)(dyn + OFF_AH);
    __nv_bfloat16* Al = (__nv_bfloat16*)(dyn + OFF_AL);
    __nv_bfloat16* Bh = (__nv_bfloat16*)(dyn + OFF_BH);
    __nv_bfloat16* Bl = (__nv_bfloat16*)(dyn + OFF_BL);

    int tid = threadIdx.x, lane = tid & 31, wid = tid >> 5;
    int wm = wid & 3, wn = wid >> 2;
    int m0 = blockIdx.x * 128;
    int n0 = blockIdx.y * 64;

    const __nv_bfloat16* ath = g_att_hi + (size_t)m0 * HID;
    const __nv_bfloat16* atl = g_att_lo + (size_t)m0 * HID;
    const __nv_bfloat16* lwh = g_lw_hi + (size_t)n0 * HID;
    const __nv_bfloat16* lwl = g_lw_lo + (size_t)n0 * HID;

    uint32_t aBaseH = smem_u32(Ah) + ((wm * 32 + (lane & 15)) * RS + (lane >> 4) * 8) * 2;
    uint32_t aBaseL = aBaseH + (OFF_AL - OFF_AH);
    uint32_t bBaseH = smem_u32(Bh) + ((wn * 32 + (lane & 7)) * RS + ((lane >> 3) & 1) * 8) * 2;
    uint32_t bBaseL = bBaseH + (OFF_BL - OFF_BH);

    float c[2][4][4];
    #pragma unroll
    for (int f = 0; f < 2; ++f)
        #pragma unroll
        for (int g = 0; g < 4; ++g)
            #pragma unroll
            for (int q = 0; q < 4; ++q) c[f][g][q] = 0.f;

    for (int ch = 0; ch < 16; ++ch) {
        int k0 = ch * 64;
        #pragma unroll
        for (int i = 0; i < 4; ++i) {
            int vi = i * 256 + tid;
            int row = vi >> 3, cu = vi & 7;
            size_t goff = (size_t)row * HID + k0 + cu * 8;
            int off = row * RS + cu * 8;
            *(uint4*)(Ah + off) = *(const uint4*)(ath + goff);
            *(uint4*)(Al + off) = *(const uint4*)(atl + goff);
        }
        #pragma unroll
        for (int i = 0; i < 2; ++i) {
            int vi = i * 256 + tid;
            int row = vi >> 3, cu = vi & 7;
            size_t goff = (size_t)row * HID + k0 + cu * 8;
            int off = row * RS + cu * 8;
            *(uint4*)(Bh + off) = *(const uint4*)(lwh + goff);
            *(uint4*)(Bl + off) = *(const uint4*)(lwl + goff);
        }
        __syncthreads();
        #pragma unroll
        for (int ks = 0; ks < 4; ++ks) {
            uint32_t ah[2][4], al[2][4], bh[4][2], bl[4][2];
            #pragma unroll
            for (int f = 0; f < 2; ++f) {
                uint32_t o = (uint32_t)(f * 16 * RS + ks * 16) * 2;
                ldsm4(ah[f], aBaseH + o);
                ldsm4(al[f], aBaseL + o);
            }
            #pragma unroll
            for (int g = 0; g < 4; ++g) {
                uint32_t o = (uint32_t)(g * 8 * RS + ks * 16) * 2;
                ldsm2(bh[g], bBaseH + o);
                ldsm2(bl[g], bBaseL + o);
            }
            #pragma unroll
            for (int f = 0; f < 2; ++f)
                #pragma unroll
                for (int g = 0; g < 4; ++g) {
                    mma16816(c[f][g], ah[f], bh[g]);
                    mma16816(c[f][g], ah[f], bl[g]);
                    mma16816(c[f][g], al[f], bh[g]);
                }
        }
        __syncthreads();
    }

    #pragma unroll
    for (int f = 0; f < 2; ++f) {
        int m = m0 + wm * 32 + f * 16 + (lane >> 2);
        #pragma unroll
        for (int g = 0; g < 4; ++g) {
            int nn = n0 + wn * 32 + g * 8 + (lane & 3) * 2;
            float b0 = lb[nn], b1 = lb[nn + 1];
            float r0 = c[f][g][0] + b0, r1 = c[f][g][1] + b1;
            float r2 = c[f][g][2] + b0, r3 = c[f][g][3] + b1;
            *(float2*)(out + (size_t)m * OUT_DIM + nn) =
                make_float2(r0 > 0.f ? r0 : 0.f, r1 > 0.f ? r1 : 0.f);
            *(float2*)(out + (size_t)(m + 8) * OUT_DIM + nn) =
                make_float2(r2 > 0.f ? r2 : 0.f, r3 > 0.f ? r3 : 0.f);
        }
    }
}

// ---------------------------------------------------------------------------
// Launch
// ---------------------------------------------------------------------------
extern "C" void kernel_launch(void* const* d_in, const int* in_sizes, int n_in,
                              void* d_out, int out_size) {
    const float* x    = (const float*)d_in[0];
    const int*   mask = (const int*)d_in[1];
    const float* W    = (const float*)d_in[2];
    const float* lw   = (const float*)d_in[3];
    const float* lb   = (const float*)d_in[4];
    float*       out  = (float*)d_out;

    const int SINK_SMEM = 512 * OUT_SIZE * 4;   // 128 KB
    cudaFuncSetAttribute(gemm_k_mma, cudaFuncAttributeMaxDynamicSharedMemorySize, DSMEM_BYTES);
    cudaFuncSetAttribute(attn_mma,   cudaFuncAttributeMaxDynamicSharedMemorySize, DSMEM_BYTES);
    cudaFuncSetAttribute(linear_mma, cudaFuncAttributeMaxDynamicSharedMemorySize, DSMEM_BYTES);
    cudaFuncSetAttribute(sinkhorn_cluster, cudaFuncAttributeMaxDynamicSharedMemorySize, SINK_SMEM);

    xsplit_kernel<<<dim3(IN_SIZE / 64, IN_DIM / 64, BATCH), 256>>>(x);
    lwsplit_kernel<<<(OUT_DIM * HID / 4) / 256, 256>>>(lw);
    gemm_k_mma<<<dim3(IN_SIZE / 128, NMAT), 256, DSMEM_BYTES>>>(x, W);
    sinkhorn_cluster<<<NMAT * 2, 512, SINK_SMEM>>>(mask);
    kut_kernel<<<dim3(IN_SIZE / 64, NMAT), 256>>>();
    attn_mma<<<dim3(IN_DIM / 128, NMAT), 256, DSMEM_BYTES>>>();
    linear_mma<<<dim3(BATCH * OUT_SIZE / 128, OUT_DIM / 64), 256, DSMEM_BYTES>>>(lb, out);
}

// round 10
// speedup vs baseline: 1.1343x; 1.1343x over previous
#include <cuda_runtime.h>
#include <cuda_bf16.h>
#include <math.h>
#include <stdint.h>

#define BATCH    64
#define IN_SIZE  1024
#define IN_DIM   256
#define HEADS    4
#define OUT_SIZE 64
#define OUT_DIM  256
#define NMAT     (BATCH * HEADS)     /* 256 */
#define HID      (HEADS * IN_DIM)    /* 1024 */
#define MAX_ITER 10

// ---------------------------------------------------------------------------
// Scratch
// ---------------------------------------------------------------------------
__device__ float g_K[(size_t)NMAT * IN_SIZE * OUT_SIZE];        // 64 MB [n][s][o]
__device__ float g_v[(size_t)NMAT * OUT_SIZE];
__device__ __nv_bfloat16 g_xT_hi[(size_t)BATCH * IN_DIM * IN_SIZE];   // [b][d][s]
__device__ __nv_bfloat16 g_xT_lo[(size_t)BATCH * IN_DIM * IN_SIZE];
__device__ __nv_bfloat16 g_kT_hi[(size_t)NMAT * OUT_SIZE * IN_SIZE];  // [n][o][s]
__device__ __nv_bfloat16 g_kT_lo[(size_t)NMAT * OUT_SIZE * IN_SIZE];
__device__ __nv_bfloat16 g_att_hi[(size_t)BATCH * OUT_SIZE * HID];    // [m][k]
__device__ __nv_bfloat16 g_att_lo[(size_t)BATCH * OUT_SIZE * HID];
__device__ __nv_bfloat16 g_lw_hi[(size_t)OUT_DIM * HID];              // [nn][k]
__device__ __nv_bfloat16 g_lw_lo[(size_t)OUT_DIM * HID];

// ---------------------------------------------------------------------------
// Helpers (base-target PTX only)
// ---------------------------------------------------------------------------
__device__ __forceinline__ uint32_t smem_u32(const void* p) {
    uint32_t a;
    asm("{ .reg .u64 t; cvta.to.shared.u64 t, %1; cvt.u32.u64 %0, t; }" : "=r"(a) : "l"(p));
    return a;
}
__device__ __forceinline__ void ldsm4(uint32_t* r, uint32_t a) {
    asm volatile("ldmatrix.sync.aligned.m8n8.x4.shared.b16 {%0,%1,%2,%3}, [%4];"
        : "=r"(r[0]), "=r"(r[1]), "=r"(r[2]), "=r"(r[3]) : "r"(a));
}
__device__ __forceinline__ void ldsm2(uint32_t* r, uint32_t a) {
    asm volatile("ldmatrix.sync.aligned.m8n8.x2.shared.b16 {%0,%1}, [%2];"
        : "=r"(r[0]), "=r"(r[1]) : "r"(a));
}
__device__ __forceinline__ void mma16816(float* c, const uint32_t* a, const uint32_t* b) {
    asm volatile(
        "mma.sync.aligned.m16n8k16.row.col.f32.bf16.bf16.f32 "
        "{%0,%1,%2,%3}, {%4,%5,%6,%7}, {%8,%9}, {%0,%1,%2,%3};"
        : "+f"(c[0]), "+f"(c[1]), "+f"(c[2]), "+f"(c[3])
        : "r"(a[0]), "r"(a[1]), "r"(a[2]), "r"(a[3]), "r"(b[0]), "r"(b[1]));
}
__device__ __forceinline__ uint32_t pack2(__nv_bfloat16 a, __nv_bfloat16 b) {
    uint16_t ua = *(uint16_t*)&a, ub = *(uint16_t*)&b;
    return (uint32_t)ua | ((uint32_t)ub << 16);
}
__device__ __forceinline__ void split2(float f, __nv_bfloat16& h, __nv_bfloat16& l) {
    h = __float2bfloat16(f);
    l = __float2bfloat16(f - __bfloat162float(h));
}

// Padded bf16 SMEM tiles for MMA kernels: row stride 72 elems (144 B).
#define RS 72
#define OFF_AH 0
#define OFF_AL (128 * RS * 2)
#define OFF_BH (2 * 128 * RS * 2)
#define OFF_BL (2 * 128 * RS * 2 + 64 * RS * 2)
#define DSMEM_BYTES (2 * 128 * RS * 2 + 2 * 64 * RS * 2)   /* 55296 */

// Sinkhorn SMEM-K stride: 67 (odd) -> scalar access conflict-free both ways.
#define KST 67
#define SINK_BYTES (512 * KST * 4)    /* 137216 */

// ---------------------------------------------------------------------------
// Kernel 1: K = exp(10 * x·Wᵀ), bf16 split-2 HMMA. M=128(s) N=64(o) K=256(d).
// ---------------------------------------------------------------------------
__global__ __launch_bounds__(256) void gemm_k_mma(const float* __restrict__ x,
                                                  const float* __restrict__ W) {
    extern __shared__ char dyn[];
    __nv_bfloat16* Ah = (__nv_bfloat16*)(dyn + OFF_AH);
    __nv_bfloat16* Al = (__nv_bfloat16*)(dyn + OFF_AL);
    __nv_bfloat16* Bh = (__nv_bfloat16*)(dyn + OFF_BH);
    __nv_bfloat16* Bl = (__nv_bfloat16*)(dyn + OFF_BL);

    int tid = threadIdx.x, lane = tid & 31, wid = tid >> 5;
    int wm = wid & 3, wn = wid >> 2;
    int n = blockIdx.y, b = n >> 2, h = n & 3;
    int s0 = blockIdx.x * 128;
    const float* xg = x + ((size_t)b * IN_SIZE + s0) * IN_DIM;
    const float* wg = W + (size_t)h * OUT_SIZE * IN_DIM;

    uint32_t aBaseH = smem_u32(Ah) + ((wm * 32 + (lane & 15)) * RS + (lane >> 4) * 8) * 2;
    uint32_t aBaseL = aBaseH + (OFF_AL - OFF_AH);
    uint32_t bBaseH = smem_u32(Bh) + ((wn * 32 + (lane & 7)) * RS + ((lane >> 3) & 1) * 8) * 2;
    uint32_t bBaseL = bBaseH + (OFF_BL - OFF_BH);

    float c[2][4][4];
    #pragma unroll
    for (int f = 0; f < 2; ++f)
        #pragma unroll
        for (int g = 0; g < 4; ++g)
            #pragma unroll
            for (int q = 0; q < 4; ++q) c[f][g][q] = 0.f;

    for (int ch = 0; ch < 4; ++ch) {
        int d0 = ch * 64;
        #pragma unroll
        for (int i = 0; i < 8; ++i) {
            int vi = i * 256 + tid;
            int row = vi >> 4, c4 = (vi & 15) * 4;
            float4 v = *(const float4*)(xg + (size_t)row * IN_DIM + d0 + c4);
            __nv_bfloat16 h0, h1, h2, h3, l0, l1, l2, l3;
            split2(v.x, h0, l0); split2(v.y, h1, l1);
            split2(v.z, h2, l2); split2(v.w, h3, l3);
            int off = row * RS + c4;
            *(uint2*)(Ah + off) = make_uint2(pack2(h0, h1), pack2(h2, h3));
            *(uint2*)(Al + off) = make_uint2(pack2(l0, l1), pack2(l2, l3));
        }
        #pragma unroll
        for (int i = 0; i < 4; ++i) {
            int vi = i * 256 + tid;
            int row = vi >> 4, c4 = (vi & 15) * 4;
            float4 v = *(const float4*)(wg + (size_t)row * IN_DIM + d0 + c4);
            __nv_bfloat16 h0, h1, h2, h3, l0, l1, l2, l3;
            split2(v.x, h0, l0); split2(v.y, h1, l1);
            split2(v.z, h2, l2); split2(v.w, h3, l3);
            int off = row * RS + c4;
            *(uint2*)(Bh + off) = make_uint2(pack2(h0, h1), pack2(h2, h3));
            *(uint2*)(Bl + off) = make_uint2(pack2(l0, l1), pack2(l2, l3));
        }
        __syncthreads();
        #pragma unroll
        for (int ks = 0; ks < 4; ++ks) {
            uint32_t ah[2][4], al[2][4], bh[4][2], bl[4][2];
            #pragma unroll
            for (int f = 0; f < 2; ++f) {
                uint32_t o = (uint32_t)(f * 16 * RS + ks * 16) * 2;
                ldsm4(ah[f], aBaseH + o);
                ldsm4(al[f], aBaseL + o);
            }
            #pragma unroll
            for (int g = 0; g < 4; ++g) {
                uint32_t o = (uint32_t)(g * 8 * RS + ks * 16) * 2;
                ldsm2(bh[g], bBaseH + o);
                ldsm2(bl[g], bBaseL + o);
            }
            #pragma unroll
            for (int f = 0; f < 2; ++f)
                #pragma unroll
                for (int g = 0; g < 4; ++g) {
                    mma16816(c[f][g], ah[f], bh[g]);
                    mma16816(c[f][g], ah[f], bl[g]);
                    mma16816(c[f][g], al[f], bh[g]);
                }
        }
        __syncthreads();
    }

    #pragma unroll
    for (int f = 0; f < 2; ++f) {
        int r0 = s0 + wm * 32 + f * 16 + (lane >> 2);
        #pragma unroll
        for (int g = 0; g < 4; ++g) {
            int o = wn * 32 + g * 8 + (lane & 3) * 2;
            float* p0 = g_K + ((size_t)n * IN_SIZE + r0) * OUT_SIZE + o;
            float* p1 = p0 + 8 * OUT_SIZE;
            *(float2*)p0 = make_float2(expf(c[f][g][0] * 10.f), expf(c[f][g][1] * 10.f));
            *(float2*)p1 = make_float2(expf(c[f][g][2] * 10.f), expf(c[f][g][3] * 10.f));
        }
    }
}

// ---------------------------------------------------------------------------
// Kernel 2: x[b][s][d] fp32 -> g_xT_hi/lo[b][d][s] bf16
// ---------------------------------------------------------------------------
__global__ __launch_bounds__(256) void xsplit_kernel(const float* __restrict__ x) {
    __shared__ float sm[64][65];
    int tid = threadIdx.x;
    int s0 = blockIdx.x * 64, d0 = blockIdx.y * 64, b = blockIdx.z;
    const float* xb = x + ((size_t)b * IN_SIZE + s0) * IN_DIM + d0;
    #pragma unroll
    for (int i = 0; i < 4; ++i) {
        int vi = i * 256 + tid;
        int rs = vi >> 4, c4 = (vi & 15) * 4;
        float4 v = *(const float4*)(xb + (size_t)rs * IN_DIM + c4);
        sm[rs][c4] = v.x; sm[rs][c4 + 1] = v.y; sm[rs][c4 + 2] = v.z; sm[rs][c4 + 3] = v.w;
    }
    __syncthreads();
    #pragma unroll
    for (int i = 0; i < 4; ++i) {
        int vi = i * 256 + tid;
        int rd = vi >> 4, s4 = (vi & 15) * 4;
        __nv_bfloat16 h[4], l[4];
        #pragma unroll
        for (int j = 0; j < 4; ++j) split2(sm[s4 + j][rd], h[j], l[j]);
        size_t off = ((size_t)b * IN_DIM + d0 + rd) * IN_SIZE + s0 + s4;
        *(uint2*)(g_xT_hi + off) = make_uint2(pack2(h[0], h[1]), pack2(h[2], h[3]));
        *(uint2*)(g_xT_lo + off) = make_uint2(pack2(l[0], l[1]), pack2(l[2], l[3]));
    }
}

// ---------------------------------------------------------------------------
// Kernel 3: Sinkhorn fused, 2-CTA cluster, K SMEM-resident (stride-67 pad),
// shuffle-free conflict-free u/v passes, + fused (u⊙K)ᵀ bf16 epilogue.
// Rank r owns rows [r*512, r*512+512). 1024 threads.
// ---------------------------------------------------------------------------
__global__ void __cluster_dims__(2, 1, 1) __launch_bounds__(1024, 1)
sinkhorn_fused(const int* __restrict__ mask) {
    extern __shared__ float sK[];          // 512 x 67 fp32 = 134 KB
    __shared__ float sm_mask[512];
    __shared__ float sm_v[OUT_SIZE];
    __shared__ float sm_u[512];
    __shared__ float sm_ph[2][512];
    __shared__ float sm_vacc[16][OUT_SIZE];
    __shared__ float sm_exch[2][OUT_SIZE];
    __shared__ float sm_red[32];
    __shared__ float sm_a;

    int tid = threadIdx.x, lane = tid & 31, wid = tid >> 5;
    uint32_t rank;
    asm("mov.u32 %0, %%cluster_ctarank;" : "=r"(rank));
    int n = blockIdx.x >> 1;
    int b = n >> 2;
    int srow0 = (int)rank * 512;

    // mask: each thread covers one global s; local rows stored by owning half.
    float m = (mask[(size_t)b * IN_SIZE + tid] != 0) ? 1.f : 0.f;
    if ((uint32_t)(tid >> 9) == rank) sm_mask[tid & 511] = m;
    float s = m;
    #pragma unroll
    for (int off = 16; off; off >>= 1) s += __shfl_xor_sync(0xffffffffu, s, off);
    if (lane == 0) sm_red[wid] = s;
    if (tid < OUT_SIZE) sm_v[tid] = 1.0f;
    __syncthreads();
    if (tid == 0) {
        float t = 0.f;
        #pragma unroll
        for (int w = 0; w < 32; ++w) t += sm_red[w];
        sm_a = (float)OUT_SIZE / t;
    }

    // Load local K half (512 x 64 fp32) into padded SMEM
    {
        const float4* g4 = (const float4*)(g_K + ((size_t)n * IN_SIZE + srow0) * OUT_SIZE);
        #pragma unroll
        for (int i = 0; i < 8; ++i) {
            int idx = i * 1024 + tid;
            int row = idx >> 4, q = idx & 15;
            float4 v = g4[idx];
            float* d = sK + row * KST + q * 4;
            d[0] = v.x; d[1] = v.y; d[2] = v.z; d[3] = v.w;
        }
    }
    __syncthreads();
    float a = sm_a;

    int half = tid >> 9;           // 0/1: o-half for u-pass
    int r = tid & 511;             // row for u-pass
    int o = tid & 63, rg = tid >> 6;   // v-pass: 16 row-groups x 64 o

    for (int it = 0; it < MAX_ITER; ++it) {
        // --- u-pass: thread = (row, o-half), 32 scalar conflict-free LDS ---
        {
            const float* kr = sK + r * KST + half * 32;
            const float* vv = sm_v + half * 32;
            float p0 = 0.f, p1 = 0.f;
            #pragma unroll
            for (int j = 0; j < 32; j += 2) {
                p0 = fmaf(kr[j], vv[j], p0);
                p1 = fmaf(kr[j + 1], vv[j + 1], p1);
            }
            sm_ph[half][r] = p0 + p1;
        }
        __syncthreads();
        if (tid < 512) {
            float p = sm_ph[0][tid] + sm_ph[1][tid];
            sm_u[tid] = sm_mask[tid] * (a / p);
        }
        __syncthreads();
        // --- v-pass: thread = (o, row-group of 32), conflict-free ---
        {
            const float* kc = sK + (rg * 32) * KST + o;
            const float* uu = sm_u + rg * 32;
            float va = 0.f;
            #pragma unroll
            for (int j = 0; j < 32; ++j) va = fmaf(uu[j], kc[j * KST], va);
            sm_vacc[rg][o] = va;
        }
        __syncthreads();
        float own = 0.f;
        if (tid < OUT_SIZE) {
            #pragma unroll
            for (int w = 0; w < 16; ++w) own += sm_vacc[w][tid];
            sm_exch[it & 1][tid] = own;
        }
        asm volatile("barrier.cluster.arrive.aligned;" ::: "memory");
        asm volatile("barrier.cluster.wait.aligned;" ::: "memory");
        if (tid < OUT_SIZE) {
            uint32_t la = smem_u32(&sm_exch[it & 1][tid]);
            uint32_t pa;
            asm("mapa.shared::cluster.u32 %0, %1, %2;" : "=r"(pa) : "r"(la), "r"(1u - rank));
            float pv;
            asm volatile("ld.shared::cluster.f32 %0, [%1];" : "=f"(pv) : "r"(pa));
            sm_v[tid] = 1.0f / (own + pv);
        }
        __syncthreads();
    }

    // Epilogue 1: v out (rank 0)
    if (rank == 0 && tid < OUT_SIZE) g_v[(size_t)n * OUT_SIZE + tid] = sm_v[tid];

    // Epilogue 2: (u⊙K)ᵀ bf16 hi/lo, warp-per-o, coalesced 128B stores.
    #pragma unroll
    for (int pass = 0; pass < 2; ++pass) {
        int oo = pass * 32 + wid;
        size_t obase = (((size_t)n * OUT_SIZE + oo) * IN_SIZE + srow0) >> 1;  // uint index
        uint32_t* dh = (uint32_t*)g_kT_hi + obase;
        uint32_t* dl = (uint32_t*)g_kT_lo + obase;
        #pragma unroll
        for (int k = 0; k < 8; ++k) {
            int sr = 64 * k + 2 * lane;
            float w0 = sm_u[sr]     * sK[sr * KST + oo];
            float w1 = sm_u[sr + 1] * sK[(sr + 1) * KST + oo];
            __nv_bfloat16 h0, l0, h1, l1;
            split2(w0, h0, l0); split2(w1, h1, l1);
            dh[32 * k + lane] = pack2(h0, h1);
            dl[32 * k + lane] = pack2(l0, l1);
        }
    }

    // No CTA may exit while the peer might still read DSMEM.
    asm volatile("barrier.cluster.arrive.aligned;" ::: "memory");
    asm volatile("barrier.cluster.wait.aligned;" ::: "memory");
}

// ---------------------------------------------------------------------------
// Kernel 4: attention: D[d,o] = Σ_s xT[d,s]·(uK)T[o,s]; att bf16 hi/lo out.
// ---------------------------------------------------------------------------
__global__ __launch_bounds__(256) void attn_mma() {
    extern __shared__ char dyn[];
    __nv_bfloat16* Ah = (__nv_bfloat16*)(dyn + OFF_AH);
    __nv_bfloat16* Al = (__nv_bfloat16*)(dyn + OFF_AL);
    __nv_bfloat16* Bh = (__nv_bfloat16*)(dyn + OFF_BH);
    __nv_bfloat16* Bl = (__nv_bfloat16*)(dyn + OFF_BL);
    __shared__ float s_v[OUT_SIZE];

    int tid = threadIdx.x, lane = tid & 31, wid = tid >> 5;
    int wm = wid & 3, wn = wid >> 2;
    int n = blockIdx.y, b = n >> 2, h = n & 3;
    int d0 = blockIdx.x * 128;

    if (tid < OUT_SIZE) s_v[tid] = g_v[(size_t)n * OUT_SIZE + tid];

    const __nv_bfloat16* xh = g_xT_hi + ((size_t)b * IN_DIM + d0) * IN_SIZE;
    const __nv_bfloat16* xl = g_xT_lo + ((size_t)b * IN_DIM + d0) * IN_SIZE;
    const __nv_bfloat16* kh = g_kT_hi + (size_t)n * OUT_SIZE * IN_SIZE;
    const __nv_bfloat16* kl = g_kT_lo + (size_t)n * OUT_SIZE * IN_SIZE;

    uint32_t aBaseH = smem_u32(Ah) + ((wm * 32 + (lane & 15)) * RS + (lane >> 4) * 8) * 2;
    uint32_t aBaseL = aBaseH + (OFF_AL - OFF_AH);
    uint32_t bBaseH = smem_u32(Bh) + ((wn * 32 + (lane & 7)) * RS + ((lane >> 3) & 1) * 8) * 2;
    uint32_t bBaseL = bBaseH + (OFF_BL - OFF_BH);

    float c[2][4][4];
    #pragma unroll
    for (int f = 0; f < 2; ++f)
        #pragma unroll
        for (int g = 0; g < 4; ++g)
            #pragma unroll
            for (int q = 0; q < 4; ++q) c[f][g][q] = 0.f;

    for (int ch = 0; ch < 16; ++ch) {
        int s0 = ch * 64;
        #pragma unroll
        for (int i = 0; i < 4; ++i) {
            int vi = i * 256 + tid;
            int row = vi >> 3, cu = vi & 7;
            size_t goff = (size_t)row * IN_SIZE + s0 + cu * 8;
            int off = row * RS + cu * 8;
            *(uint4*)(Ah + off) = *(const uint4*)(xh + goff);
            *(uint4*)(Al + off) = *(const uint4*)(xl + goff);
        }
        #pragma unroll
        for (int i = 0; i < 2; ++i) {
            int vi = i * 256 + tid;
            int row = vi >> 3, cu = vi & 7;
            size_t goff = (size_t)row * IN_SIZE + s0 + cu * 8;
            int off = row * RS + cu * 8;
            *(uint4*)(Bh + off) = *(const uint4*)(kh + goff);
            *(uint4*)(Bl + off) = *(const uint4*)(kl + goff);
        }
        __syncthreads();
        #pragma unroll
        for (int ks = 0; ks < 4; ++ks) {
            uint32_t ah[2][4], al[2][4], bh[4][2], bl[4][2];
            #pragma unroll
            for (int f = 0; f < 2; ++f) {
                uint32_t o = (uint32_t)(f * 16 * RS + ks * 16) * 2;
                ldsm4(ah[f], aBaseH + o);
                ldsm4(al[f], aBaseL + o);
            }
            #pragma unroll
            for (int g = 0; g < 4; ++g) {
                uint32_t o = (uint32_t)(g * 8 * RS + ks * 16) * 2;
                ldsm2(bh[g], bBaseH + o);
                ldsm2(bl[g], bBaseL + o);
            }
            #pragma unroll
            for (int f = 0; f < 2; ++f)
                #pragma unroll
                for (int g = 0; g < 4; ++g) {
                    mma16816(c[f][g], ah[f], bh[g]);
                    mma16816(c[f][g], ah[f], bl[g]);
                    mma16816(c[f][g], al[f], bh[g]);
                }
        }
        __syncthreads();
    }

    // Epilogue: v-scale, transpose via SMEM, emit bf16 hi/lo att[m][k]
    float* smF = (float*)dyn;   // 128 x 65 fp32
    #pragma unroll
    for (int f = 0; f < 2; ++f) {
        int dl = wm * 32 + f * 16 + (lane >> 2);
        #pragma unroll
        for (int g = 0; g < 4; ++g) {
            int o = wn * 32 + g * 8 + (lane & 3) * 2;
            smF[dl * 65 + o]           = s_v[o]     * c[f][g][0];
            smF[dl * 65 + o + 1]       = s_v[o + 1] * c[f][g][1];
            smF[(dl + 8) * 65 + o]     = s_v[o]     * c[f][g][2];
            smF[(dl + 8) * 65 + o + 1] = s_v[o + 1] * c[f][g][3];
        }
    }
    __syncthreads();
    {
        int o = tid >> 2;
        int dseg = (tid & 3) * 32;
        size_t rowbase = ((size_t)b * OUT_SIZE + o) * HID + (size_t)h * IN_DIM + d0 + dseg;
        #pragma unroll
        for (int j = 0; j < 8; ++j) {
            float f0 = smF[(dseg + 4 * j + 0) * 65 + o];
            float f1 = smF[(dseg + 4 * j + 1) * 65 + o];
            float f2 = smF[(dseg + 4 * j + 2) * 65 + o];
            float f3 = smF[(dseg + 4 * j + 3) * 65 + o];
            __nv_bfloat16 h0, h1, h2, h3, l0, l1, l2, l3;
            split2(f0, h0, l0); split2(f1, h1, l1);
            split2(f2, h2, l2); split2(f3, h3, l3);
            *(uint2*)(g_att_hi + rowbase + 4 * j) = make_uint2(pack2(h0, h1), pack2(h2, h3));
            *(uint2*)(g_att_lo + rowbase + 4 * j) = make_uint2(pack2(l0, l1), pack2(l2, l3));
        }
    }
}

// ---------------------------------------------------------------------------
// Kernel 5: lin_w fp32 -> bf16 hi/lo
// ---------------------------------------------------------------------------
__global__ __launch_bounds__(256) void lwsplit_kernel(const float* __restrict__ lw) {
    int i = blockIdx.x * 256 + threadIdx.x;
    float4 v = *(const float4*)(lw + (size_t)i * 4);
    __nv_bfloat16 h0, h1, h2, h3, l0, l1, l2, l3;
    split2(v.x, h0, l0); split2(v.y, h1, l1);
    split2(v.z, h2, l2); split2(v.w, h3, l3);
    *(uint2*)(g_lw_hi + (size_t)i * 4) = make_uint2(pack2(h0, h1), pack2(h2, h3));
    *(uint2*)(g_lw_lo + (size_t)i * 4) = make_uint2(pack2(l0, l1), pack2(l2, l3));
}

// ---------------------------------------------------------------------------
// Kernel 6: out = relu(att @ lin_wᵀ + lin_b), bf16 split-2 HMMA.
// ---------------------------------------------------------------------------
__global__ __launch_bounds__(256) void linear_mma(const float* __restrict__ lb,
                                                  float* __restrict__ out) {
    extern __shared__ char dyn[];
    __nv_bfloat16* Ah = (__nv_bfloat16*)(dyn + OFF_AH);
    __nv_bfloat16* Al = (__nv_bfloat16*)(dyn + OFF_AL);
    __nv_bfloat16* Bh = (__nv_bfloat16*)(dyn + OFF_BH);
    __nv_bfloat16* Bl = (__nv_bfloat16*)(dyn + OFF_BL);

    int tid = threadIdx.x, lane = tid & 31, wid = tid >> 5;
    int wm = wid & 3, wn = wid >> 2;
    int m0 = blockIdx.x * 128;
    int n0 = blockIdx.y * 64;

    const __nv_bfloat16* ath = g_att_hi + (size_t)m0 * HID;
    const __nv_bfloat16* atl = g_att_lo + (size_t)m0 * HID;
    const __nv_bfloat16* lwh = g_lw_hi + (size_t)n0 * HID;
    const __nv_bfloat16* lwl = g_lw_lo + (size_t)n0 * HID;

    uint32_t aBaseH = smem_u32(Ah) + ((wm * 32 + (lane & 15)) * RS + (lane >> 4) * 8) * 2;
    uint32_t aBaseL = aBaseH + (OFF_AL - OFF_AH);
    uint32_t bBaseH = smem_u32(Bh) + ((wn * 32 + (lane & 7)) * RS + ((lane >> 3) & 1) * 8) * 2;
    uint32_t bBaseL = bBaseH + (OFF_BL - OFF_BH);

    float c[2][4][4];
    #pragma unroll
    for (int f = 0; f < 2; ++f)
        #pragma unroll
        for (int g = 0; g < 4; ++g)
            #pragma unroll
            for (int q = 0; q < 4; ++q) c[f][g][q] = 0.f;

    for (int ch = 0; ch < 16; ++ch) {
        int k0 = ch * 64;
        #pragma unroll
        for (int i = 0; i < 4; ++i) {
            int vi = i * 256 + tid;
            int row = vi >> 3, cu = vi & 7;
            size_t goff = (size_t)row * HID + k0 + cu * 8;
            int off = row * RS + cu * 8;
            *(uint4*)(Ah + off) = *(const uint4*)(ath + goff);
            *(uint4*)(Al + off) = *(const uint4*)(atl + goff);
        }
        #pragma unroll
        for (int i = 0; i < 2; ++i) {
            int vi = i * 256 + tid;
            int row = vi >> 3, cu = vi & 7;
            size_t goff = (size_t)row * HID + k0 + cu * 8;
            int off = row * RS + cu * 8;
            *(uint4*)(Bh + off) = *(const uint4*)(lwh + goff);
            *(uint4*)(Bl + off) = *(const uint4*)(lwl + goff);
        }
        __syncthreads();
        #pragma unroll
        for (int ks = 0; ks < 4; ++ks) {
            uint32_t ah[2][4], al[2][4], bh[4][2], bl[4][2];
            #pragma unroll
            for (int f = 0; f < 2; ++f) {
                uint32_t o = (uint32_t)(f * 16 * RS + ks * 16) * 2;
                ldsm4(ah[f], aBaseH + o);
                ldsm4(al[f], aBaseL + o);
            }
            #pragma unroll
            for (int g = 0; g < 4; ++g) {
                uint32_t o = (uint32_t)(g * 8 * RS + ks * 16) * 2;
                ldsm2(bh[g], bBaseH + o);
                ldsm2(bl[g], bBaseL + o);
            }
            #pragma unroll
            for (int f = 0; f < 2; ++f)
                #pragma unroll
                for (int g = 0; g < 4; ++g) {
                    mma16816(c[f][g], ah[f], bh[g]);
                    mma16816(c[f][g], ah[f], bl[g]);
                    mma16816(c[f][g], al[f], bh[g]);
                }
        }
        __syncthreads();
    }

    #pragma unroll
    for (int f = 0; f < 2; ++f) {
        int m = m0 + wm * 32 + f * 16 + (lane >> 2);
        #pragma unroll
        for (int g = 0; g < 4; ++g) {
            int nn = n0 + wn * 32 + g * 8 + (lane & 3) * 2;
            float b0 = lb[nn], b1 = lb[nn + 1];
            float r0 = c[f][g][0] + b0, r1 = c[f][g][1] + b1;
            float r2 = c[f][g][2] + b0, r3 = c[f][g][3] + b1;
            *(float2*)(out + (size_t)m * OUT_DIM + nn) =
                make_float2(r0 > 0.f ? r0 : 0.f, r1 > 0.f ? r1 : 0.f);
            *(float2*)(out + (size_t)(m + 8) * OUT_DIM + nn) =
                make_float2(r2 > 0.f ? r2 : 0.f, r3 > 0.f ? r3 : 0.f);
        }
    }
}

// ---------------------------------------------------------------------------
// Launch
// ---------------------------------------------------------------------------
extern "C" void kernel_launch(void* const* d_in, const int* in_sizes, int n_in,
                              void* d_out, int out_size) {
    const float* x    = (const float*)d_in[0];
    const int*   mask = (const int*)d_in[1];
    const float* W    = (const float*)d_in[2];
    const float* lw   = (const float*)d_in[3];
    const float* lb   = (const float*)d_in[4];
    float*       out  = (float*)d_out;

    cudaFuncSetAttribute(gemm_k_mma, cudaFuncAttributeMaxDynamicSharedMemorySize, DSMEM_BYTES);
    cudaFuncSetAttribute(attn_mma,   cudaFuncAttributeMaxDynamicSharedMemorySize, DSMEM_BYTES);
    cudaFuncSetAttribute(linear_mma, cudaFuncAttributeMaxDynamicSharedMemorySize, DSMEM_BYTES);
    cudaFuncSetAttribute(sinkhorn_fused, cudaFuncAttributeMaxDynamicSharedMemorySize, SINK_BYTES);

    xsplit_kernel<<<dim3(IN_SIZE / 64, IN_DIM / 64, BATCH), 256>>>(x);
    lwsplit_kernel<<<(OUT_DIM * HID / 4) / 256, 256>>>(lw);
    gemm_k_mma<<<dim3(IN_SIZE / 128, NMAT), 256, DSMEM_BYTES>>>(x, W);
    sinkhorn_fused<<<NMAT * 2, 1024, SINK_BYTES>>>(mask);
    attn_mma<<<dim3(IN_DIM / 128, NMAT), 256, DSMEM_BYTES>>>();
    linear_mma<<<dim3(BATCH * OUT_SIZE / 128, OUT_DIM / 64), 256, DSMEM_BYTES>>>(lb, out);
}